// round 1
// baseline (speedup 1.0000x reference)
#include <cuda_runtime.h>
#include <cuda_bf16.h>
#include <cstddef>

// Problem constants
#define Bz 4
#define Lz 2048
#define Ez 1024
#define Hz 16
#define DKz 64
#define Mz (Bz * Lz)   // 8192

// ---------------- scratch (allocation-free: __device__ globals) --------------
__device__ float g_Q[(size_t)Mz * Ez];
__device__ float g_K[(size_t)Mz * Ez];
__device__ float g_V[(size_t)Mz * Ez];
__device__ float g_CTX[(size_t)Mz * Ez];

// ---------------- GEMM: C[m,n] = sum_k A[m,k] * W[n,k] + bias[n] -------------
// A: [M, K] row-major, W: [N, K] row-major (torch Linear weight)
// permute==1: write to [B, H, L, DK] layout (for Q/K/V), else [M, N] row-major.
#define BM 128
#define BN 128
#define BK 16

__global__ __launch_bounds__(256) void gemm_nt_kernel(
    const float* __restrict__ A, const float* __restrict__ W,
    const float* __restrict__ bias, float* __restrict__ C,
    int M, int N, int K, int permute)
{
    __shared__ float As[BK][BM];
    __shared__ float Bs[BK][BN];

    const int tid = threadIdx.x;
    const int m0 = blockIdx.y * BM;
    const int n0 = blockIdx.x * BN;
    const int tm = (tid >> 4) << 3;   // 0..120, step 8
    const int tn = (tid & 15) << 3;   // 0..120, step 8

    float acc[8][8];
#pragma unroll
    for (int i = 0; i < 8; i++)
#pragma unroll
        for (int j = 0; j < 8; j++) acc[i][j] = 0.f;

    for (int k0 = 0; k0 < K; k0 += BK) {
        // load 128x16 A tile + 128x16 W tile (512 float4 each, 2 per thread)
#pragma unroll
        for (int t = 0; t < 2; t++) {
            int i   = tid + t * 256;
            int row = i >> 2;
            int c4  = (i & 3) << 2;
            float4 va = *(const float4*)&A[(size_t)(m0 + row) * K + k0 + c4];
            As[c4 + 0][row] = va.x; As[c4 + 1][row] = va.y;
            As[c4 + 2][row] = va.z; As[c4 + 3][row] = va.w;
            float4 vb = *(const float4*)&W[(size_t)(n0 + row) * K + k0 + c4];
            Bs[c4 + 0][row] = vb.x; Bs[c4 + 1][row] = vb.y;
            Bs[c4 + 2][row] = vb.z; Bs[c4 + 3][row] = vb.w;
        }
        __syncthreads();

#pragma unroll
        for (int kk = 0; kk < BK; kk++) {
            float a[8], b[8];
            *(float4*)&a[0] = *(const float4*)&As[kk][tm];
            *(float4*)&a[4] = *(const float4*)&As[kk][tm + 4];
            *(float4*)&b[0] = *(const float4*)&Bs[kk][tn];
            *(float4*)&b[4] = *(const float4*)&Bs[kk][tn + 4];
#pragma unroll
            for (int i = 0; i < 8; i++)
#pragma unroll
                for (int j = 0; j < 8; j++)
                    acc[i][j] += a[i] * b[j];
        }
        __syncthreads();
    }

    // epilogue: add bias, store (optionally permuted to [B,H,L,DK])
#pragma unroll
    for (int i = 0; i < 8; i++) {
        int m = m0 + tm + i;
#pragma unroll
        for (int j = 0; j < 8; j += 4) {
            int n = n0 + tn + j;
            float4 r;
            r.x = acc[i][j + 0] + bias[n + 0];
            r.y = acc[i][j + 1] + bias[n + 1];
            r.z = acc[i][j + 2] + bias[n + 2];
            r.w = acc[i][j + 3] + bias[n + 3];
            if (!permute) {
                *(float4*)&C[(size_t)m * N + n] = r;
            } else {
                int b = m >> 11;          // / L (2048)
                int l = m & 2047;
                int h = n >> 6;           // / DK (64)
                int d = n & 63;
                size_t o = (((size_t)(b * Hz + h)) * Lz + l) * DKz + d;
                *(float4*)&C[o] = r;
            }
        }
    }
}

// ---------------- Flash attention (causal), fp32 -----------------------------
// Q/K/V in [B,H,L,DK]; output ctx written in [B,L,E] (= [B,L,H,DK]) layout.
#define AQ 128   // queries per CTA (== blockDim.x)
#define AK 64    // keys per smem tile

__global__ __launch_bounds__(128) void attn_kernel(
    const float* __restrict__ Q, const float* __restrict__ K,
    const float* __restrict__ V, float* __restrict__ O,
    const int* __restrict__ causal_p)
{
    __shared__ float Ks[AK * DKz];
    __shared__ float Vs[AK * DKz];

    const int bh  = blockIdx.y;           // 0..63
    const int qb  = blockIdx.x;           // 0..15
    const int tid = threadIdx.x;
    const int q   = qb * AQ + tid;        // query row within [0, L)
    const float scale = 0.125f;           // 1/sqrt(64)
    const size_t base = (size_t)bh * Lz * DKz;
    const int causal = *causal_p;

    // load this thread's q row, fold in scale
    float4 qv[16];
    const float4* qp = (const float4*)&Q[base + (size_t)q * DKz];
#pragma unroll
    for (int i = 0; i < 16; i++) {
        float4 v = qp[i];
        v.x *= scale; v.y *= scale; v.z *= scale; v.w *= scale;
        qv[i] = v;
    }
    float4 av[16];
#pragma unroll
    for (int i = 0; i < 16; i++) av[i] = make_float4(0.f, 0.f, 0.f, 0.f);
    float mmax = -1e30f, lsum = 0.f;

    const int ntiles = causal ? (qb * AQ + AQ) / AK : (Lz / AK);

    for (int t = 0; t < ntiles; t++) {
        const float4* kg = (const float4*)&K[base + (size_t)t * AK * DKz];
        const float4* vg = (const float4*)&V[base + (size_t)t * AK * DKz];
#pragma unroll
        for (int r = 0; r < 8; r++) {
            int i = tid + r * 128;   // 0..1023 float4 index
            ((float4*)Ks)[i] = kg[i];
            ((float4*)Vs)[i] = vg[i];
        }
        __syncthreads();

        int smax = causal ? min(AK, q - t * AK + 1) : AK;
        for (int s = 0; s < smax; s++) {
            const float4* kr = (const float4*)&Ks[s * DKz];
            float sc = 0.f;
#pragma unroll
            for (int i = 0; i < 16; i++) {
                float4 kv = kr[i];
                sc += qv[i].x * kv.x + qv[i].y * kv.y
                    + qv[i].z * kv.z + qv[i].w * kv.w;
            }
            float p;
            if (sc > mmax) {
                float corr = __expf(mmax - sc);
                mmax = sc;
                lsum *= corr;
#pragma unroll
                for (int i = 0; i < 16; i++) {
                    av[i].x *= corr; av[i].y *= corr;
                    av[i].z *= corr; av[i].w *= corr;
                }
                p = 1.f;
            } else {
                p = __expf(sc - mmax);
            }
            lsum += p;
            const float4* vr = (const float4*)&Vs[s * DKz];
#pragma unroll
            for (int i = 0; i < 16; i++) {
                float4 vv = vr[i];
                av[i].x += p * vv.x; av[i].y += p * vv.y;
                av[i].z += p * vv.z; av[i].w += p * vv.w;
            }
        }
        __syncthreads();
    }

    float inv = 1.f / lsum;
    // write ctx[b, l, h*DK + d]
    int b = bh >> 4, h = bh & 15;
    float* op = &O[((size_t)(b * Lz + q)) * Ez + h * DKz];
#pragma unroll
    for (int i = 0; i < 16; i++) {
        float4 r = av[i];
        r.x *= inv; r.y *= inv; r.z *= inv; r.w *= inv;
        ((float4*)op)[i] = r;
    }
}

// ---------------- launch ------------------------------------------------------
extern "C" void kernel_launch(void* const* d_in, const int* in_sizes, int n_in,
                              void* d_out, int out_size)
{
    (void)in_sizes; (void)n_in; (void)out_size;
    const float* query = (const float*)d_in[0];
    const float* key   = (const float*)d_in[1];
    const float* value = (const float*)d_in[2];
    const float* wq    = (const float*)d_in[3];
    const float* bq    = (const float*)d_in[4];
    const float* wk    = (const float*)d_in[5];
    const float* bk    = (const float*)d_in[6];
    const float* wv    = (const float*)d_in[7];
    const float* bv    = (const float*)d_in[8];
    const float* wo    = (const float*)d_in[9];
    const float* bo    = (const float*)d_in[10];
    const int*   isc   = (const int*)d_in[11];
    float* out = (float*)d_out;

    float *qS, *kS, *vS, *cS;
    cudaGetSymbolAddress((void**)&qS, g_Q);
    cudaGetSymbolAddress((void**)&kS, g_K);
    cudaGetSymbolAddress((void**)&vS, g_V);
    cudaGetSymbolAddress((void**)&cS, g_CTX);

    dim3 gg(Ez / BN, Mz / BM);   // (8, 64)
    gemm_nt_kernel<<<gg, 256>>>(query, wq, bq, qS, Mz, Ez, Ez, 1);
    gemm_nt_kernel<<<gg, 256>>>(key,   wk, bk, kS, Mz, Ez, Ez, 1);
    gemm_nt_kernel<<<gg, 256>>>(value, wv, bv, vS, Mz, Ez, Ez, 1);

    attn_kernel<<<dim3(Lz / AQ, Bz * Hz), 128>>>(qS, kS, vS, cS, isc);

    gemm_nt_kernel<<<gg, 256>>>(cS, wo, bo, out, Mz, Ez, Ez, 0);
}

// round 3
// speedup vs baseline: 1.5578x; 1.5578x over previous
#include <cuda_runtime.h>
#include <cuda_bf16.h>
#include <cstdint>
#include <cstddef>

// Problem constants
#define Bz 4
#define Lz 2048
#define Ez 1024
#define Hz 16
#define DKz 64
#define Mz (Bz * Lz)   // 8192

// ---------------- scratch (allocation-free: __device__ globals) --------------
__device__ float g_Q[(size_t)Mz * Ez];
__device__ float g_K[(size_t)Mz * Ez];
__device__ float g_V[(size_t)Mz * Ez];
__device__ float g_CTX[(size_t)Mz * Ez];

// ============================ PTX helpers (base ISA only) ====================
__device__ __forceinline__ uint32_t smem_u32(const void* p) {
    uint32_t a;
    asm("{ .reg .u64 t; cvta.to.shared.u64 t, %1; cvt.u32.u64 %0, t; }"
        : "=r"(a) : "l"(p));
    return a;
}
#define CP_ASYNC16(dst, src) \
    asm volatile("cp.async.cg.shared.global [%0], [%1], 16;" :: "r"(dst), "l"(src))
#define CP_COMMIT() asm volatile("cp.async.commit_group;" ::: "memory")
#define CP_WAIT_1() asm volatile("cp.async.wait_group 1;" ::: "memory")

#define LDSM_X4(r0, r1, r2, r3, addr) \
    asm volatile("ldmatrix.sync.aligned.m8n8.x4.shared.b16 {%0,%1,%2,%3}, [%4];" \
        : "=r"(r0), "=r"(r1), "=r"(r2), "=r"(r3) : "r"(addr))

#define CVT_TF32(x) asm("cvt.rna.tf32.f32 %0, %0;" : "+r"(x))

#define MMA_TF32(d, a, bv0, bv1) \
    asm volatile("mma.sync.aligned.m16n8k8.row.col.f32.tf32.tf32.f32 " \
        "{%0,%1,%2,%3}, {%4,%5,%6,%7}, {%8,%9}, {%0,%1,%2,%3};" \
        : "+f"((d)[0]), "+f"((d)[1]), "+f"((d)[2]), "+f"((d)[3]) \
        : "r"((a)[0]), "r"((a)[1]), "r"((a)[2]), "r"((a)[3]), "r"(bv0), "r"(bv1))

// ====================== tf32 mma.sync GEMM ===================================
// C[m,n] = sum_k A[m,k] * W[n,k] + bias[n]   (A:[M,K] rm, W:[N,K] rm)
// CTA tile 128x128, BK=32 floats, double-buffered cp.async, 8 warps (4m x 2n).
#define TM 128
#define TN 128
#define BKf 32
#define NKCH (Ez / BKf)            // 32
#define ASTG (TM * BKf * 4)        // 16384 B per stage
#define BSTG (TN * BKf * 4)        // 16384 B per stage
#define GEMM_SMEM (2 * (ASTG + BSTG))  // 65536 B

// stage: 128 rows x 8 chunks of 16B; smem row stride 128B; chunk ^= (row&7)
__device__ __forceinline__ void ld_stage(uint32_t dstbase, const float* __restrict__ src,
                                         int tid)
{
#pragma unroll
    for (int i = 0; i < 4; i++) {
        int idx = tid + i * 256;
        int row = idx >> 3, ch = idx & 7;
        uint32_t dst = dstbase + row * 128 + ((ch ^ (row & 7)) << 4);
        CP_ASYNC16(dst, src + (size_t)row * Ez + ch * 4);
    }
}

__global__ void __launch_bounds__(256, 2) gemm_tc_kernel(
    const float* __restrict__ A, const float* __restrict__ W,
    const float* __restrict__ bias, float* __restrict__ C, int permute)
{
    extern __shared__ char smem[];
    const uint32_t sb = smem_u32(smem);
    const uint32_t sA0 = sb,             sA1 = sb + ASTG;
    const uint32_t sB0 = sb + 2 * ASTG,  sB1 = sb + 2 * ASTG + BSTG;

    const int tid  = threadIdx.x;
    const int wid  = tid >> 5, lane = tid & 31;
    const int wm   = wid & 3;          // warp m index (0..3) -> rows wm*32
    const int wn   = wid >> 2;         // warp n index (0..1) -> cols wn*64
    const int lj   = lane & 7;         // ldmatrix row-within-matrix
    const int lm   = lane >> 3;        // ldmatrix matrix index (0..3)
    const int m0   = blockIdx.y * TM, n0 = blockIdx.x * TN;

    const float* Ag = A + (size_t)m0 * Ez;
    const float* Wg = W + (size_t)n0 * Ez;

    float acc[2][8][4];
#pragma unroll
    for (int mt = 0; mt < 2; mt++)
#pragma unroll
        for (int nt = 0; nt < 8; nt++)
#pragma unroll
            for (int j = 0; j < 4; j++) acc[mt][nt][j] = 0.f;

    // prologue
    ld_stage(sA0, Ag + 0 * BKf, tid); ld_stage(sB0, Wg + 0 * BKf, tid); CP_COMMIT();
    ld_stage(sA1, Ag + 1 * BKf, tid); ld_stage(sB1, Wg + 1 * BKf, tid); CP_COMMIT();

    // per-thread ldmatrix base addresses (chunk swizzle applied per k-step)
    // A matrices: row = wm*32 + mt*16 + (lm&1)*8 + lj ; chunk = ks*2 + (lm>>1)
    // B matrices: row = wn*64 + p*16 + (lm>>1)*8 + lj ; chunk = ks*2 + (lm&1)
    const uint32_t aRow = (uint32_t)(wm * 32 + (lm & 1) * 8 + lj) * 128;
    const uint32_t bRow = (uint32_t)(wn * 64 + (lm >> 1) * 8 + lj) * 128;
    const int aChHi = lm >> 1;   // chunk offset parity for A
    const int bChHi = lm & 1;    // chunk offset parity for B

#pragma unroll 1
    for (int k = 0; k < NKCH; k++) {
        const int st = k & 1;
        const uint32_t sA = st ? sA1 : sA0;
        const uint32_t sB = st ? sB1 : sB0;
        CP_WAIT_1();
        __syncthreads();

#pragma unroll
        for (int ks = 0; ks < 4; ks++) {
            uint32_t ar[2][4];
#pragma unroll
            for (int mt = 0; mt < 2; mt++) {
                uint32_t addr = sA + aRow + mt * (16 * 128)
                              + (uint32_t)(((ks * 2 + aChHi) ^ lj) << 4);
                LDSM_X4(ar[mt][0], ar[mt][1], ar[mt][2], ar[mt][3], addr);
            }
            uint32_t br[4][4];
#pragma unroll
            for (int p = 0; p < 4; p++) {
                uint32_t addr = sB + bRow + p * (16 * 128)
                              + (uint32_t)(((ks * 2 + bChHi) ^ lj) << 4);
                LDSM_X4(br[p][0], br[p][1], br[p][2], br[p][3], addr);
            }
#pragma unroll
            for (int mt = 0; mt < 2; mt++)
#pragma unroll
                for (int j = 0; j < 4; j++) CVT_TF32(ar[mt][j]);
#pragma unroll
            for (int p = 0; p < 4; p++)
#pragma unroll
                for (int j = 0; j < 4; j++) CVT_TF32(br[p][j]);

#pragma unroll
            for (int mt = 0; mt < 2; mt++)
#pragma unroll
                for (int nt = 0; nt < 8; nt++) {
                    const int p = nt >> 1, h = (nt & 1) * 2;
                    MMA_TF32(acc[mt][nt], ar[mt], br[p][h], br[p][h + 1]);
                }
        }
        __syncthreads();
        if (k + 2 < NKCH) {
            ld_stage(st ? sA1 : sA0, Ag + (size_t)(k + 2) * BKf, tid);
            ld_stage(st ? sB1 : sB0, Wg + (size_t)(k + 2) * BKf, tid);
        }
        CP_COMMIT();
    }

    // epilogue: C fragment: rows g, g+8 ; cols 2*(lane%4), +1
    const int g  = lane >> 2;
    const int cq = (lane & 3) * 2;
#pragma unroll
    for (int mt = 0; mt < 2; mt++) {
#pragma unroll
        for (int nt = 0; nt < 8; nt++) {
            const int n = n0 + wn * 64 + nt * 8 + cq;
            const float bx = bias[n], by = bias[n + 1];
#pragma unroll
            for (int half = 0; half < 2; half++) {
                const int m = m0 + wm * 32 + mt * 16 + g + half * 8;
                float2 v;
                v.x = acc[mt][nt][half * 2 + 0] + bx;
                v.y = acc[mt][nt][half * 2 + 1] + by;
                if (!permute) {
                    *(float2*)&C[(size_t)m * Ez + n] = v;
                } else {
                    int b = m >> 11, l = m & 2047, h = n >> 6, d = n & 63;
                    *(float2*)&C[(((size_t)(b * Hz + h)) * Lz + l) * DKz + d] = v;
                }
            }
        }
    }
}

// ---------------- Flash attention (causal), fp32 -----------------------------
#define AQ 128
#define AK 64

__global__ __launch_bounds__(128) void attn_kernel(
    const float* __restrict__ Q, const float* __restrict__ K,
    const float* __restrict__ V, float* __restrict__ O,
    const int* __restrict__ causal_p)
{
    __shared__ float Ks[AK * DKz];
    __shared__ float Vs[AK * DKz];

    const int bh  = blockIdx.y;
    const int qb  = blockIdx.x;
    const int tid = threadIdx.x;
    const int q   = qb * AQ + tid;
    const float scale = 0.125f;
    const size_t base = (size_t)bh * Lz * DKz;
    const int causal = *causal_p;

    float4 qv[16];
    const float4* qp = (const float4*)&Q[base + (size_t)q * DKz];
#pragma unroll
    for (int i = 0; i < 16; i++) {
        float4 v = qp[i];
        v.x *= scale; v.y *= scale; v.z *= scale; v.w *= scale;
        qv[i] = v;
    }
    float4 av[16];
#pragma unroll
    for (int i = 0; i < 16; i++) av[i] = make_float4(0.f, 0.f, 0.f, 0.f);
    float mmax = -1e30f, lsum = 0.f;

    const int ntiles = causal ? (qb * AQ + AQ) / AK : (Lz / AK);

    for (int t = 0; t < ntiles; t++) {
        const float4* kg = (const float4*)&K[base + (size_t)t * AK * DKz];
        const float4* vg = (const float4*)&V[base + (size_t)t * AK * DKz];
#pragma unroll
        for (int r = 0; r < 8; r++) {
            int i = tid + r * 128;
            ((float4*)Ks)[i] = kg[i];
            ((float4*)Vs)[i] = vg[i];
        }
        __syncthreads();

        int smax = causal ? min(AK, q - t * AK + 1) : AK;
        for (int s = 0; s < smax; s++) {
            const float4* kr = (const float4*)&Ks[s * DKz];
            float sc = 0.f;
#pragma unroll
            for (int i = 0; i < 16; i++) {
                float4 kv = kr[i];
                sc += qv[i].x * kv.x + qv[i].y * kv.y
                    + qv[i].z * kv.z + qv[i].w * kv.w;
            }
            float p;
            if (sc > mmax) {
                float corr = __expf(mmax - sc);
                mmax = sc;
                lsum *= corr;
#pragma unroll
                for (int i = 0; i < 16; i++) {
                    av[i].x *= corr; av[i].y *= corr;
                    av[i].z *= corr; av[i].w *= corr;
                }
                p = 1.f;
            } else {
                p = __expf(sc - mmax);
            }
            lsum += p;
            const float4* vr = (const float4*)&Vs[s * DKz];
#pragma unroll
            for (int i = 0; i < 16; i++) {
                float4 vv = vr[i];
                av[i].x += p * vv.x; av[i].y += p * vv.y;
                av[i].z += p * vv.z; av[i].w += p * vv.w;
            }
        }
        __syncthreads();
    }

    float inv = 1.f / lsum;
    int b = bh >> 4, h = bh & 15;
    float* op = &O[((size_t)(b * Lz + q)) * Ez + h * DKz];
#pragma unroll
    for (int i = 0; i < 16; i++) {
        float4 r = av[i];
        r.x *= inv; r.y *= inv; r.z *= inv; r.w *= inv;
        ((float4*)op)[i] = r;
    }
}

// ---------------- launch ------------------------------------------------------
extern "C" void kernel_launch(void* const* d_in, const int* in_sizes, int n_in,
                              void* d_out, int out_size)
{
    (void)in_sizes; (void)n_in; (void)out_size;
    const float* query = (const float*)d_in[0];
    const float* key   = (const float*)d_in[1];
    const float* value = (const float*)d_in[2];
    const float* wq    = (const float*)d_in[3];
    const float* bq    = (const float*)d_in[4];
    const float* wk    = (const float*)d_in[5];
    const float* bk    = (const float*)d_in[6];
    const float* wv    = (const float*)d_in[7];
    const float* bv    = (const float*)d_in[8];
    const float* wo    = (const float*)d_in[9];
    const float* bo    = (const float*)d_in[10];
    const int*   isc   = (const int*)d_in[11];
    float* out = (float*)d_out;

    float *qS, *kS, *vS, *cS;
    cudaGetSymbolAddress((void**)&qS, g_Q);
    cudaGetSymbolAddress((void**)&kS, g_K);
    cudaGetSymbolAddress((void**)&vS, g_V);
    cudaGetSymbolAddress((void**)&cS, g_CTX);

    cudaFuncSetAttribute(gemm_tc_kernel,
                         cudaFuncAttributeMaxDynamicSharedMemorySize, GEMM_SMEM);

    dim3 gg(Ez / TN, Mz / TM);   // (8, 64) = 512 CTAs
    gemm_tc_kernel<<<gg, 256, GEMM_SMEM>>>(query, wq, bq, qS, 1);
    gemm_tc_kernel<<<gg, 256, GEMM_SMEM>>>(key,   wk, bk, kS, 1);
    gemm_tc_kernel<<<gg, 256, GEMM_SMEM>>>(value, wv, bv, vS, 1);

    attn_kernel<<<dim3(Lz / AQ, Bz * Hz), 128>>>(qS, kS, vS, cS, isc);

    gemm_tc_kernel<<<gg, 256, GEMM_SMEM>>>(cS, wo, bo, out, 0);
}

// round 4
// speedup vs baseline: 6.0171x; 3.8626x over previous
#include <cuda_runtime.h>
#include <cuda_fp16.h>
#include <cstdint>
#include <cstddef>

// Problem constants
#define Bz 4
#define Lz 2048
#define Ez 1024
#define Hz 16
#define DKz 64
#define Mz (Bz * Lz)   // 8192

// ---------------- scratch (allocation-free: __device__ globals) --------------
__device__ __half g_Qh[(size_t)Mz * Ez];
__device__ __half g_Kh[(size_t)Mz * Ez];
__device__ __half g_Vh[(size_t)Mz * Ez];
__device__ float  g_CTX[(size_t)Mz * Ez];
__device__ float  g_AR[(size_t)3 * Mz * Ez];   // pre-rounded query,key,value
__device__ float  g_WR[(size_t)4 * Ez * Ez];   // pre-rounded wq,wk,wv,wo

// ============================ PTX helpers (base ISA only) ====================
__device__ __forceinline__ uint32_t smem_u32(const void* p) {
    uint32_t a;
    asm("{ .reg .u64 t; cvta.to.shared.u64 t, %1; cvt.u32.u64 %0, t; }"
        : "=r"(a) : "l"(p));
    return a;
}
#define CP_ASYNC16(dst, src) \
    asm volatile("cp.async.cg.shared.global [%0], [%1], 16;" :: "r"(dst), "l"(src))
#define CP_COMMIT() asm volatile("cp.async.commit_group;" ::: "memory")
#define CP_WAIT_1() asm volatile("cp.async.wait_group 1;" ::: "memory")

#define LDSM_X4(r0, r1, r2, r3, addr) \
    asm volatile("ldmatrix.sync.aligned.m8n8.x4.shared.b16 {%0,%1,%2,%3}, [%4];" \
        : "=r"(r0), "=r"(r1), "=r"(r2), "=r"(r3) : "r"(addr))
#define LDSM_X4T(r0, r1, r2, r3, addr) \
    asm volatile("ldmatrix.sync.aligned.m8n8.x4.trans.shared.b16 {%0,%1,%2,%3}, [%4];" \
        : "=r"(r0), "=r"(r1), "=r"(r2), "=r"(r3) : "r"(addr))

#define CVT_TF32U(x) asm("cvt.rna.tf32.f32 %0, %0;" : "+r"(x))

#define MMA_TF32(d, a, bv0, bv1) \
    asm volatile("mma.sync.aligned.m16n8k8.row.col.f32.tf32.tf32.f32 " \
        "{%0,%1,%2,%3}, {%4,%5,%6,%7}, {%8,%9}, {%0,%1,%2,%3};" \
        : "+f"((d)[0]), "+f"((d)[1]), "+f"((d)[2]), "+f"((d)[3]) \
        : "r"((a)[0]), "r"((a)[1]), "r"((a)[2]), "r"((a)[3]), "r"(bv0), "r"(bv1))

#define MMA_F16(d, a, bv0, bv1) \
    asm volatile("mma.sync.aligned.m16n8k16.row.col.f32.f16.f16.f32 " \
        "{%0,%1,%2,%3}, {%4,%5,%6,%7}, {%8,%9}, {%0,%1,%2,%3};" \
        : "+f"((d)[0]), "+f"((d)[1]), "+f"((d)[2]), "+f"((d)[3]) \
        : "r"((a)[0]), "r"((a)[1]), "r"((a)[2]), "r"((a)[3]), "r"(bv0), "r"(bv1))

__device__ __forceinline__ uint32_t packh2(float a, float b) {
    __half2 h = __floats2half2_rn(a, b);
    return *(uint32_t*)&h;
}
__device__ __forceinline__ float round_tf32f(float x) {
    uint32_t u = __float_as_uint(x);
    CVT_TF32U(u);
    return __uint_as_float(u);
}

// ====================== tf32 pre-round pass ==================================
__global__ void __launch_bounds__(256) round_tf32_kernel(
    float* __restrict__ dst, const float* __restrict__ src, int n4)
{
    int i = blockIdx.x * blockDim.x + threadIdx.x;
    if (i >= n4) return;
    float4 v = ((const float4*)src)[i];
    v.x = round_tf32f(v.x); v.y = round_tf32f(v.y);
    v.z = round_tf32f(v.z); v.w = round_tf32f(v.w);
    ((float4*)dst)[i] = v;
}

// ====================== tf32 mma.sync GEMM ===================================
// C[m,n] = (sum_k A[m,k] * W[n,k] + bias[n]) * oscale
// A, W pre-rounded to tf32. omode 0: fp32 [M,E]; omode 1: fp16 [B,H,L,DK].
#define TM 128
#define TN 128
#define BKf 32
#define NKCH (Ez / BKf)            // 32
#define ASTG (TM * BKf * 4)        // 16384 B per stage
#define BSTG (TN * BKf * 4)
#define GEMM_SMEM (2 * (ASTG + BSTG))  // 65536 B

__device__ __forceinline__ void ld_stage(uint32_t dstbase, const float* __restrict__ src,
                                         int tid)
{
#pragma unroll
    for (int i = 0; i < 4; i++) {
        int idx = tid + i * 256;
        int row = idx >> 3, ch = idx & 7;
        uint32_t dst = dstbase + row * 128 + ((ch ^ (row & 7)) << 4);
        CP_ASYNC16(dst, src + (size_t)row * Ez + ch * 4);
    }
}

__global__ void __launch_bounds__(256, 2) gemm_tc_kernel(
    const float* __restrict__ A, const float* __restrict__ W,
    const float* __restrict__ bias, void* __restrict__ Cv,
    int omode, float oscale)
{
    extern __shared__ char smem[];
    const uint32_t sb = smem_u32(smem);
    const uint32_t sA0 = sb,             sA1 = sb + ASTG;
    const uint32_t sB0 = sb + 2 * ASTG,  sB1 = sb + 2 * ASTG + BSTG;

    const int tid  = threadIdx.x;
    const int wid  = tid >> 5, lane = tid & 31;
    const int wm   = wid & 3;
    const int wn   = wid >> 2;
    const int lj   = lane & 7;
    const int lm   = lane >> 3;
    const int m0   = blockIdx.y * TM, n0 = blockIdx.x * TN;

    const float* Ag = A + (size_t)m0 * Ez;
    const float* Wg = W + (size_t)n0 * Ez;

    float acc[2][8][4];
#pragma unroll
    for (int mt = 0; mt < 2; mt++)
#pragma unroll
        for (int nt = 0; nt < 8; nt++)
#pragma unroll
            for (int j = 0; j < 4; j++) acc[mt][nt][j] = 0.f;

    ld_stage(sA0, Ag + 0 * BKf, tid); ld_stage(sB0, Wg + 0 * BKf, tid); CP_COMMIT();
    ld_stage(sA1, Ag + 1 * BKf, tid); ld_stage(sB1, Wg + 1 * BKf, tid); CP_COMMIT();

    const uint32_t aRow = (uint32_t)(wm * 32 + (lm & 1) * 8 + lj) * 128;
    const uint32_t bRow = (uint32_t)(wn * 64 + (lm >> 1) * 8 + lj) * 128;
    const int aChHi = lm >> 1;
    const int bChHi = lm & 1;

#pragma unroll 1
    for (int k = 0; k < NKCH; k++) {
        const int st = k & 1;
        const uint32_t sA = st ? sA1 : sA0;
        const uint32_t sB = st ? sB1 : sB0;
        CP_WAIT_1();
        __syncthreads();

#pragma unroll
        for (int ks = 0; ks < 4; ks++) {
            uint32_t ar[2][4];
#pragma unroll
            for (int mt = 0; mt < 2; mt++) {
                uint32_t addr = sA + aRow + mt * (16 * 128)
                              + (uint32_t)(((ks * 2 + aChHi) ^ lj) << 4);
                LDSM_X4(ar[mt][0], ar[mt][1], ar[mt][2], ar[mt][3], addr);
            }
            uint32_t br[4][4];
#pragma unroll
            for (int p = 0; p < 4; p++) {
                uint32_t addr = sB + bRow + p * (16 * 128)
                              + (uint32_t)(((ks * 2 + bChHi) ^ lj) << 4);
                LDSM_X4(br[p][0], br[p][1], br[p][2], br[p][3], addr);
            }
#pragma unroll
            for (int mt = 0; mt < 2; mt++)
#pragma unroll
                for (int nt = 0; nt < 8; nt++) {
                    const int p = nt >> 1, h2 = (nt & 1) * 2;
                    MMA_TF32(acc[mt][nt], ar[mt], br[p][h2], br[p][h2 + 1]);
                }
        }
        __syncthreads();
        if (k + 2 < NKCH) {
            ld_stage(st ? sA1 : sA0, Ag + (size_t)(k + 2) * BKf, tid);
            ld_stage(st ? sB1 : sB0, Wg + (size_t)(k + 2) * BKf, tid);
        }
        CP_COMMIT();
    }

    const int g  = lane >> 2;
    const int cq = (lane & 3) * 2;
#pragma unroll
    for (int mt = 0; mt < 2; mt++) {
#pragma unroll
        for (int nt = 0; nt < 8; nt++) {
            const int n = n0 + wn * 64 + nt * 8 + cq;
            const float bx = bias[n], by = bias[n + 1];
#pragma unroll
            for (int hf = 0; hf < 2; hf++) {
                const int m = m0 + wm * 32 + mt * 16 + g + hf * 8;
                float vx = (acc[mt][nt][hf * 2 + 0] + bx) * oscale;
                float vy = (acc[mt][nt][hf * 2 + 1] + by) * oscale;
                if (omode == 0) {
                    float2 v; v.x = vx; v.y = vy;
                    *(float2*)&((float*)Cv)[(size_t)m * Ez + n] = v;
                } else {
                    int b = m >> 11, l = m & 2047, hh = n >> 6, d = n & 63;
                    __half2 hv = __floats2half2_rn(vx, vy);
                    *(__half2*)&((__half*)Cv)[(((size_t)(b * Hz + hh)) * Lz + l) * DKz + d] = hv;
                }
            }
        }
    }
}

// ================= fp16 tensor-core flash attention (FA2-style) ==============
// Q,K,V: fp16 [B,H,L,DK] (Q pre-scaled by 1/8). O: fp32 [B,L,E], tf32-rounded.
// CTA: 128 threads (4 warps); tile 64 queries x full DK=64; key tiles of 64.
#define ATILE 4096   // 64 rows * 64 halves

__device__ __forceinline__ void ldtile16(uint32_t dst, const __half* __restrict__ src,
                                         int tid)
{
#pragma unroll
    for (int i = 0; i < 4; i++) {
        int idx = tid + i * 128;
        int row = idx >> 3, ch = idx & 7;
        CP_ASYNC16(dst + row * 128 + ((ch ^ (row & 7)) << 4),
                   src + (size_t)row * DKz + ch * 8);
    }
}

__global__ void __launch_bounds__(128) attn_f16_kernel(
    const __half* __restrict__ Q, const __half* __restrict__ K,
    const __half* __restrict__ V, float* __restrict__ O,
    const int* __restrict__ causal_p)
{
    __shared__ char sm[5 * 8192];   // Q + 2x K + 2x V
    const uint32_t sQ = smem_u32(sm);
    const uint32_t sK0 = sQ + 8192,  sK1 = sQ + 16384;
    const uint32_t sV0 = sQ + 24576, sV1 = sQ + 32768;

    const int tid = threadIdx.x, lane = tid & 31, wm = tid >> 5;
    const int lj = lane & 7, lm = lane >> 3;
    const int g = lane >> 2, cq = (lane & 3) * 2;
    const int qt = blockIdx.x, bh = blockIdx.y;
    const int q0 = qt * 64;
    const int causal = *causal_p;
    const int ntiles = causal ? (qt + 1) : (Lz / 64);

    const size_t base = (size_t)bh * Lz * DKz;
    const __half* Qg = Q + base + (size_t)q0 * DKz;
    const __half* Kg = K + base;
    const __half* Vg = V + base;

    ldtile16(sQ, Qg, tid);
    ldtile16(sK0, Kg, tid);
    ldtile16(sV0, Vg, tid);
    CP_COMMIT();
    if (ntiles > 1) { ldtile16(sK1, Kg + ATILE, tid); ldtile16(sV1, Vg + ATILE, tid); }
    CP_COMMIT();

    uint32_t aq[4][4];
    float oacc[8][4];
#pragma unroll
    for (int nt = 0; nt < 8; nt++)
#pragma unroll
        for (int j = 0; j < 4; j++) oacc[nt][j] = 0.f;
    float M0 = -1e30f, M1 = -1e30f, ls0 = 0.f, ls1 = 0.f;

    const int rowA = q0 + wm * 16 + g;     // this thread's first q row
    const uint32_t aqRow = (uint32_t)(wm * 16 + (lm & 1) * 8 + lj) * 128;

#pragma unroll 1
    for (int t = 0; t < ntiles; t++) {
        const uint32_t sK = (t & 1) ? sK1 : sK0;
        const uint32_t sV = (t & 1) ? sV1 : sV0;
        CP_WAIT_1();
        __syncthreads();

        if (t == 0) {
#pragma unroll
            for (int ks = 0; ks < 4; ks++) {
                uint32_t addr = sQ + aqRow
                              + (uint32_t)(((ks * 2 + (lm >> 1)) ^ lj) << 4);
                LDSM_X4(aq[ks][0], aq[ks][1], aq[ks][2], aq[ks][3], addr);
            }
        }

        // ---- S = Q K^T ----
        float sacc[8][4];
#pragma unroll
        for (int nt = 0; nt < 8; nt++)
#pragma unroll
            for (int j = 0; j < 4; j++) sacc[nt][j] = 0.f;

        const uint32_t bkRowBase = (uint32_t)((lm >> 1) * 8 + lj) * 128;
#pragma unroll
        for (int ks = 0; ks < 4; ks++) {
            uint32_t bk[4][4];
#pragma unroll
            for (int p = 0; p < 4; p++) {
                uint32_t row = p * 16 * 128 + bkRowBase;
                uint32_t rr = (p * 16 + (lm >> 1) * 8 + lj) & 7;
                uint32_t addr = sK + row + (uint32_t)(((ks * 2 + (lm & 1)) ^ rr) << 4);
                LDSM_X4(bk[p][0], bk[p][1], bk[p][2], bk[p][3], addr);
            }
#pragma unroll
            for (int p = 0; p < 4; p++) {
                MMA_F16(sacc[2 * p],     aq[ks], bk[p][0], bk[p][1]);
                MMA_F16(sacc[2 * p + 1], aq[ks], bk[p][2], bk[p][3]);
            }
        }

        // ---- causal mask (diagonal tile only) ----
        if (causal && t == qt) {
            const int colb = t * 64 + cq;
#pragma unroll
            for (int nt = 0; nt < 8; nt++) {
                int c = colb + nt * 8;
                if (c     > rowA)     sacc[nt][0] = -1e30f;
                if (c + 1 > rowA)     sacc[nt][1] = -1e30f;
                if (c     > rowA + 8) sacc[nt][2] = -1e30f;
                if (c + 1 > rowA + 8) sacc[nt][3] = -1e30f;
            }
        }

        // ---- online softmax ----
        float mA = -1e30f, mB = -1e30f;
#pragma unroll
        for (int nt = 0; nt < 8; nt++) {
            mA = fmaxf(mA, fmaxf(sacc[nt][0], sacc[nt][1]));
            mB = fmaxf(mB, fmaxf(sacc[nt][2], sacc[nt][3]));
        }
        mA = fmaxf(mA, __shfl_xor_sync(0xffffffffu, mA, 1));
        mA = fmaxf(mA, __shfl_xor_sync(0xffffffffu, mA, 2));
        mB = fmaxf(mB, __shfl_xor_sync(0xffffffffu, mB, 1));
        mB = fmaxf(mB, __shfl_xor_sync(0xffffffffu, mB, 2));

        float Mn0 = fmaxf(M0, mA), Mn1 = fmaxf(M1, mB);
        float f0 = __expf(M0 - Mn0), f1 = __expf(M1 - Mn1);
        M0 = Mn0; M1 = Mn1;
        ls0 *= f0; ls1 *= f1;
#pragma unroll
        for (int nt = 0; nt < 8; nt++) {
            oacc[nt][0] *= f0; oacc[nt][1] *= f0;
            oacc[nt][2] *= f1; oacc[nt][3] *= f1;
        }

        uint32_t pa[4][4];
#pragma unroll
        for (int ks = 0; ks < 4; ks++) {
            float e00 = __expf(sacc[2 * ks][0] - M0);
            float e01 = __expf(sacc[2 * ks][1] - M0);
            float e02 = __expf(sacc[2 * ks][2] - M1);
            float e03 = __expf(sacc[2 * ks][3] - M1);
            float e10 = __expf(sacc[2 * ks + 1][0] - M0);
            float e11 = __expf(sacc[2 * ks + 1][1] - M0);
            float e12 = __expf(sacc[2 * ks + 1][2] - M1);
            float e13 = __expf(sacc[2 * ks + 1][3] - M1);
            ls0 += e00 + e01 + e10 + e11;
            ls1 += e02 + e03 + e12 + e13;
            pa[ks][0] = packh2(e00, e01);
            pa[ks][1] = packh2(e02, e03);
            pa[ks][2] = packh2(e10, e11);
            pa[ks][3] = packh2(e12, e13);
        }

        // ---- O += P V ----
        const uint32_t bvRowBase = (uint32_t)((lm & 1) * 8 + lj) * 128;
#pragma unroll
        for (int ks = 0; ks < 4; ks++) {
            uint32_t bv[4][4];
#pragma unroll
            for (int p = 0; p < 4; p++) {
                uint32_t row = ks * 16 * 128 + bvRowBase;
                uint32_t rr = (ks * 16 + (lm & 1) * 8 + lj) & 7;
                uint32_t addr = sV + row + (uint32_t)(((p * 2 + (lm >> 1)) ^ rr) << 4);
                LDSM_X4T(bv[p][0], bv[p][1], bv[p][2], bv[p][3], addr);
            }
#pragma unroll
            for (int p = 0; p < 4; p++) {
                MMA_F16(oacc[2 * p],     pa[ks], bv[p][0], bv[p][1]);
                MMA_F16(oacc[2 * p + 1], pa[ks], bv[p][2], bv[p][3]);
            }
        }

        __syncthreads();
        if (t + 2 < ntiles) {
            ldtile16((t & 1) ? sK1 : sK0, Kg + (size_t)(t + 2) * ATILE, tid);
            ldtile16((t & 1) ? sV1 : sV0, Vg + (size_t)(t + 2) * ATILE, tid);
        }
        CP_COMMIT();
    }

    // ---- epilogue: normalize, round to tf32, write ctx [B,L,E] ----
    ls0 += __shfl_xor_sync(0xffffffffu, ls0, 1);
    ls0 += __shfl_xor_sync(0xffffffffu, ls0, 2);
    ls1 += __shfl_xor_sync(0xffffffffu, ls1, 1);
    ls1 += __shfl_xor_sync(0xffffffffu, ls1, 2);
    const float inv0 = 1.f / ls0, inv1 = 1.f / ls1;

    const int b = bh >> 4, hh = bh & 15;
    float* oA = &O[((size_t)(b * Lz + rowA)) * Ez + hh * DKz];
    float* oB = &O[((size_t)(b * Lz + rowA + 8)) * Ez + hh * DKz];
#pragma unroll
    for (int nt = 0; nt < 8; nt++) {
        const int d = nt * 8 + cq;
        float2 vA, vB;
        vA.x = round_tf32f(oacc[nt][0] * inv0);
        vA.y = round_tf32f(oacc[nt][1] * inv0);
        vB.x = round_tf32f(oacc[nt][2] * inv1);
        vB.y = round_tf32f(oacc[nt][3] * inv1);
        *(float2*)&oA[d] = vA;
        *(float2*)&oB[d] = vB;
    }
}

// ---------------- launch ------------------------------------------------------
extern "C" void kernel_launch(void* const* d_in, const int* in_sizes, int n_in,
                              void* d_out, int out_size)
{
    (void)in_sizes; (void)n_in; (void)out_size;
    const float* query = (const float*)d_in[0];
    const float* key   = (const float*)d_in[1];
    const float* value = (const float*)d_in[2];
    const float* wq    = (const float*)d_in[3];
    const float* bq    = (const float*)d_in[4];
    const float* wk    = (const float*)d_in[5];
    const float* bk    = (const float*)d_in[6];
    const float* wv    = (const float*)d_in[7];
    const float* bv    = (const float*)d_in[8];
    const float* wo    = (const float*)d_in[9];
    const float* bo    = (const float*)d_in[10];
    const int*   isc   = (const int*)d_in[11];
    float* out = (float*)d_out;

    __half *qh, *kh, *vh;
    float *cS, *aR, *wR;
    cudaGetSymbolAddress((void**)&qh, g_Qh);
    cudaGetSymbolAddress((void**)&kh, g_Kh);
    cudaGetSymbolAddress((void**)&vh, g_Vh);
    cudaGetSymbolAddress((void**)&cS, g_CTX);
    cudaGetSymbolAddress((void**)&aR, g_AR);
    cudaGetSymbolAddress((void**)&wR, g_WR);

    cudaFuncSetAttribute(gemm_tc_kernel,
                         cudaFuncAttributeMaxDynamicSharedMemorySize, GEMM_SMEM);

    // pre-round activations + weights to tf32
    const int nAct4 = (Mz * Ez) / 4;      // 2M float4
    const int nW4   = (Ez * Ez) / 4;      // 256K float4
    round_tf32_kernel<<<nAct4 / 256, 256>>>(aR + 0 * (size_t)Mz * Ez, query, nAct4);
    round_tf32_kernel<<<nAct4 / 256, 256>>>(aR + 1 * (size_t)Mz * Ez, key,   nAct4);
    round_tf32_kernel<<<nAct4 / 256, 256>>>(aR + 2 * (size_t)Mz * Ez, value, nAct4);
    round_tf32_kernel<<<nW4 / 256, 256>>>(wR + 0 * (size_t)Ez * Ez, wq, nW4);
    round_tf32_kernel<<<nW4 / 256, 256>>>(wR + 1 * (size_t)Ez * Ez, wk, nW4);
    round_tf32_kernel<<<nW4 / 256, 256>>>(wR + 2 * (size_t)Ez * Ez, wv, nW4);
    round_tf32_kernel<<<nW4 / 256, 256>>>(wR + 3 * (size_t)Ez * Ez, wo, nW4);

    dim3 gg(Ez / TN, Mz / TM);   // (8, 64)
    gemm_tc_kernel<<<gg, 256, GEMM_SMEM>>>(aR + 0 * (size_t)Mz * Ez,
                                           wR + 0 * (size_t)Ez * Ez, bq, qh, 1, 0.125f);
    gemm_tc_kernel<<<gg, 256, GEMM_SMEM>>>(aR + 1 * (size_t)Mz * Ez,
                                           wR + 1 * (size_t)Ez * Ez, bk, kh, 1, 1.0f);
    gemm_tc_kernel<<<gg, 256, GEMM_SMEM>>>(aR + 2 * (size_t)Mz * Ez,
                                           wR + 2 * (size_t)Ez * Ez, bv, vh, 1, 1.0f);

    attn_f16_kernel<<<dim3(Lz / 64, Bz * Hz), 128>>>(qh, kh, vh, cS, isc);

    gemm_tc_kernel<<<gg, 256, GEMM_SMEM>>>(cS, wR + 3 * (size_t)Ez * Ez, bo, out, 0, 1.0f);
}

// round 5
// speedup vs baseline: 8.8980x; 1.4788x over previous
#include <cuda_runtime.h>
#include <cuda_fp16.h>
#include <cstdint>
#include <cstddef>

// Problem constants
#define Bz 4
#define Lz 2048
#define Ez 1024
#define Hz 16
#define DKz 64
#define Mz (Bz * Lz)   // 8192

// ---------------- scratch (allocation-free: __device__ globals) --------------
__device__ __half g_Qh[(size_t)Mz * Ez];    // [B,H,L,DK], pre-scaled by 1/8
__device__ __half g_Kh[(size_t)Mz * Ez];    // [B,H,L,DK]
__device__ __half g_Vh[(size_t)Mz * Ez];    // [B,H,L,DK]
__device__ __half g_CTXh[(size_t)Mz * Ez];  // [B,L,E] fp16 ctx
__device__ __half g_Xh[(size_t)3 * Mz * Ez];  // fp16 query,key,value
__device__ __half g_Wh[(size_t)4 * Ez * Ez];  // fp16 wq,wk,wv,wo

// ============================ PTX helpers (base ISA only) ====================
__device__ __forceinline__ uint32_t smem_u32(const void* p) {
    uint32_t a;
    asm("{ .reg .u64 t; cvta.to.shared.u64 t, %1; cvt.u32.u64 %0, t; }"
        : "=r"(a) : "l"(p));
    return a;
}
#define CP_ASYNC16(dst, src) \
    asm volatile("cp.async.cg.shared.global [%0], [%1], 16;" :: "r"(dst), "l"(src))
#define CP_COMMIT() asm volatile("cp.async.commit_group;" ::: "memory")
#define CP_WAIT_1() asm volatile("cp.async.wait_group 1;" ::: "memory")

#define LDSM_X4(r0, r1, r2, r3, addr) \
    asm volatile("ldmatrix.sync.aligned.m8n8.x4.shared.b16 {%0,%1,%2,%3}, [%4];" \
        : "=r"(r0), "=r"(r1), "=r"(r2), "=r"(r3) : "r"(addr))
#define LDSM_X4T(r0, r1, r2, r3, addr) \
    asm volatile("ldmatrix.sync.aligned.m8n8.x4.trans.shared.b16 {%0,%1,%2,%3}, [%4];" \
        : "=r"(r0), "=r"(r1), "=r"(r2), "=r"(r3) : "r"(addr))

#define MMA_F16(d, a, bv0, bv1) \
    asm volatile("mma.sync.aligned.m16n8k16.row.col.f32.f16.f16.f32 " \
        "{%0,%1,%2,%3}, {%4,%5,%6,%7}, {%8,%9}, {%0,%1,%2,%3};" \
        : "+f"((d)[0]), "+f"((d)[1]), "+f"((d)[2]), "+f"((d)[3]) \
        : "r"((a)[0]), "r"((a)[1]), "r"((a)[2]), "r"((a)[3]), "r"(bv0), "r"(bv1))

__device__ __forceinline__ uint32_t packh2(float a, float b) {
    __half2 h = __floats2half2_rn(a, b);
    return *(uint32_t*)&h;
}

// ====================== fp32 -> fp16 convert pass ============================
__global__ void __launch_bounds__(256) cvt_h_kernel(
    __half* __restrict__ dst, const float* __restrict__ src, int n8)
{
    int i = blockIdx.x * blockDim.x + threadIdx.x;
    if (i >= n8) return;
    float4 a = ((const float4*)src)[2 * i];
    float4 b = ((const float4*)src)[2 * i + 1];
    uint4 o;
    o.x = packh2(a.x, a.y); o.y = packh2(a.z, a.w);
    o.z = packh2(b.x, b.y); o.w = packh2(b.z, b.w);
    ((uint4*)dst)[i] = o;
}

// ====================== fp16 mma.sync GEMM ===================================
// C[m,n] = (sum_k A[m,k] * W[n,k] + bias[n]) * oscale
// A:[M,K] fp16 rm, W:[N,K] fp16 rm. omode 0: fp32 [M,E]; 1: fp16 [B,H,L,DK].
// CTA tile 128x128, BK=64 halves (128B rows), double-buffered, 8 warps (4m x 2n).
#define TM 128
#define TN 128
#define BKh 64
#define NKCH (Ez / BKh)            // 16
#define HSTG (128 * 64 * 2)        // 16384 B per stage per operand
#define GEMM_SMEM (4 * HSTG)       // 65536 B

__device__ __forceinline__ void ld_stage_h(uint32_t dstbase,
                                           const __half* __restrict__ src, int tid)
{
#pragma unroll
    for (int i = 0; i < 4; i++) {
        int idx = tid + i * 256;
        int row = idx >> 3, ch = idx & 7;
        uint32_t dst = dstbase + row * 128 + ((ch ^ (row & 7)) << 4);
        CP_ASYNC16(dst, src + (size_t)row * Ez + ch * 8);
    }
}

__global__ void __launch_bounds__(256, 2) gemm_h_kernel(
    const __half* __restrict__ A, const __half* __restrict__ W,
    const float* __restrict__ bias, void* __restrict__ Cv,
    int omode, float oscale)
{
    extern __shared__ char smem[];
    const uint32_t sb = smem_u32(smem);
    const uint32_t sA0 = sb,            sA1 = sb + HSTG;
    const uint32_t sB0 = sb + 2 * HSTG, sB1 = sb + 3 * HSTG;

    const int tid  = threadIdx.x;
    const int wid  = tid >> 5, lane = tid & 31;
    const int wm   = wid & 3;
    const int wn   = wid >> 2;
    const int lj   = lane & 7;
    const int lm   = lane >> 3;
    const int m0   = blockIdx.y * TM, n0 = blockIdx.x * TN;

    const __half* Ag = A + (size_t)m0 * Ez;
    const __half* Wg = W + (size_t)n0 * Ez;

    float acc[2][8][4];
#pragma unroll
    for (int mt = 0; mt < 2; mt++)
#pragma unroll
        for (int nt = 0; nt < 8; nt++)
#pragma unroll
            for (int j = 0; j < 4; j++) acc[mt][nt][j] = 0.f;

    ld_stage_h(sA0, Ag + 0 * BKh, tid); ld_stage_h(sB0, Wg + 0 * BKh, tid); CP_COMMIT();
    ld_stage_h(sA1, Ag + 1 * BKh, tid); ld_stage_h(sB1, Wg + 1 * BKh, tid); CP_COMMIT();

    const uint32_t aRow = (uint32_t)(wm * 32 + (lm & 1) * 8 + lj) * 128;
    const uint32_t bRow = (uint32_t)(wn * 64 + (lm >> 1) * 8 + lj) * 128;
    const int aChHi = lm >> 1;
    const int bChHi = lm & 1;

#pragma unroll 1
    for (int k = 0; k < NKCH; k++) {
        const int st = k & 1;
        const uint32_t sA = st ? sA1 : sA0;
        const uint32_t sB = st ? sB1 : sB0;
        CP_WAIT_1();
        __syncthreads();

#pragma unroll
        for (int ks = 0; ks < 4; ks++) {            // 4 x k16 per chunk
            uint32_t ar[2][4];
#pragma unroll
            for (int mt = 0; mt < 2; mt++) {
                uint32_t addr = sA + aRow + mt * (16 * 128)
                              + (uint32_t)(((ks * 2 + aChHi) ^ lj) << 4);
                LDSM_X4(ar[mt][0], ar[mt][1], ar[mt][2], ar[mt][3], addr);
            }
            uint32_t br[4][4];
#pragma unroll
            for (int p = 0; p < 4; p++) {
                uint32_t addr = sB + bRow + p * (16 * 128)
                              + (uint32_t)(((ks * 2 + bChHi) ^ lj) << 4);
                LDSM_X4(br[p][0], br[p][1], br[p][2], br[p][3], addr);
            }
#pragma unroll
            for (int mt = 0; mt < 2; mt++)
#pragma unroll
                for (int p = 0; p < 4; p++) {
                    MMA_F16(acc[mt][2 * p],     ar[mt], br[p][0], br[p][1]);
                    MMA_F16(acc[mt][2 * p + 1], ar[mt], br[p][2], br[p][3]);
                }
        }
        __syncthreads();
        if (k + 2 < NKCH) {
            ld_stage_h(st ? sA1 : sA0, Ag + (size_t)(k + 2) * BKh, tid);
            ld_stage_h(st ? sB1 : sB0, Wg + (size_t)(k + 2) * BKh, tid);
        }
        CP_COMMIT();
    }

    const int g  = lane >> 2;
    const int cq = (lane & 3) * 2;
#pragma unroll
    for (int mt = 0; mt < 2; mt++) {
#pragma unroll
        for (int nt = 0; nt < 8; nt++) {
            const int n = n0 + wn * 64 + nt * 8 + cq;
            const float bx = bias[n], by = bias[n + 1];
#pragma unroll
            for (int hf = 0; hf < 2; hf++) {
                const int m = m0 + wm * 32 + mt * 16 + g + hf * 8;
                float vx = (acc[mt][nt][hf * 2 + 0] + bx) * oscale;
                float vy = (acc[mt][nt][hf * 2 + 1] + by) * oscale;
                if (omode == 0) {
                    float2 v; v.x = vx; v.y = vy;
                    *(float2*)&((float*)Cv)[(size_t)m * Ez + n] = v;
                } else {
                    int b = m >> 11, l = m & 2047, hh = n >> 6, d = n & 63;
                    __half2 hv = __floats2half2_rn(vx, vy);
                    *(__half2*)&((__half*)Cv)[(((size_t)(b * Hz + hh)) * Lz + l) * DKz + d] = hv;
                }
            }
        }
    }
}

// ================= fp16 tensor-core flash attention (FA2-style) ==============
// Q,K,V: fp16 [B,H,L,DK] (Q pre-scaled by 1/8). O: fp16 [B,L,E].
#define ATILE 4096   // 64 rows * 64 halves

__device__ __forceinline__ void ldtile16(uint32_t dst, const __half* __restrict__ src,
                                         int tid)
{
#pragma unroll
    for (int i = 0; i < 4; i++) {
        int idx = tid + i * 128;
        int row = idx >> 3, ch = idx & 7;
        CP_ASYNC16(dst + row * 128 + ((ch ^ (row & 7)) << 4),
                   src + (size_t)row * DKz + ch * 8);
    }
}

__global__ void __launch_bounds__(128) attn_f16_kernel(
    const __half* __restrict__ Q, const __half* __restrict__ K,
    const __half* __restrict__ V, __half* __restrict__ O,
    const int* __restrict__ causal_p)
{
    __shared__ char sm[5 * 8192];   // Q + 2x K + 2x V
    const uint32_t sQ = smem_u32(sm);
    const uint32_t sK0 = sQ + 8192,  sK1 = sQ + 16384;
    const uint32_t sV0 = sQ + 24576, sV1 = sQ + 32768;

    const int tid = threadIdx.x, lane = tid & 31, wm = tid >> 5;
    const int lj = lane & 7, lm = lane >> 3;
    const int g = lane >> 2, cq = (lane & 3) * 2;
    const int qt = blockIdx.x, bh = blockIdx.y;
    const int q0 = qt * 64;
    const int causal = *causal_p;
    const int ntiles = causal ? (qt + 1) : (Lz / 64);

    const size_t base = (size_t)bh * Lz * DKz;
    const __half* Qg = Q + base + (size_t)q0 * DKz;
    const __half* Kg = K + base;
    const __half* Vg = V + base;

    ldtile16(sQ, Qg, tid);
    ldtile16(sK0, Kg, tid);
    ldtile16(sV0, Vg, tid);
    CP_COMMIT();
    if (ntiles > 1) { ldtile16(sK1, Kg + ATILE, tid); ldtile16(sV1, Vg + ATILE, tid); }
    CP_COMMIT();

    uint32_t aq[4][4];
    float oacc[8][4];
#pragma unroll
    for (int nt = 0; nt < 8; nt++)
#pragma unroll
        for (int j = 0; j < 4; j++) oacc[nt][j] = 0.f;
    float M0 = -1e30f, M1 = -1e30f, ls0 = 0.f, ls1 = 0.f;

    const int rowA = q0 + wm * 16 + g;
    const uint32_t aqRow = (uint32_t)(wm * 16 + (lm & 1) * 8 + lj) * 128;

#pragma unroll 1
    for (int t = 0; t < ntiles; t++) {
        const uint32_t sK = (t & 1) ? sK1 : sK0;
        const uint32_t sV = (t & 1) ? sV1 : sV0;
        CP_WAIT_1();
        __syncthreads();

        if (t == 0) {
#pragma unroll
            for (int ks = 0; ks < 4; ks++) {
                uint32_t addr = sQ + aqRow
                              + (uint32_t)(((ks * 2 + (lm >> 1)) ^ lj) << 4);
                LDSM_X4(aq[ks][0], aq[ks][1], aq[ks][2], aq[ks][3], addr);
            }
        }

        // ---- S = Q K^T ----
        float sacc[8][4];
#pragma unroll
        for (int nt = 0; nt < 8; nt++)
#pragma unroll
            for (int j = 0; j < 4; j++) sacc[nt][j] = 0.f;

        const uint32_t bkRowBase = (uint32_t)((lm >> 1) * 8 + lj) * 128;
#pragma unroll
        for (int ks = 0; ks < 4; ks++) {
            uint32_t bk[4][4];
#pragma unroll
            for (int p = 0; p < 4; p++) {
                uint32_t addr = sK + p * (16 * 128) + bkRowBase
                              + (uint32_t)(((ks * 2 + (lm & 1)) ^ lj) << 4);
                LDSM_X4(bk[p][0], bk[p][1], bk[p][2], bk[p][3], addr);
            }
#pragma unroll
            for (int p = 0; p < 4; p++) {
                MMA_F16(sacc[2 * p],     aq[ks], bk[p][0], bk[p][1]);
                MMA_F16(sacc[2 * p + 1], aq[ks], bk[p][2], bk[p][3]);
            }
        }

        // ---- causal mask (diagonal tile only) ----
        if (causal && t == qt) {
            const int colb = t * 64 + cq;
#pragma unroll
            for (int nt = 0; nt < 8; nt++) {
                int c = colb + nt * 8;
                if (c     > rowA)     sacc[nt][0] = -1e30f;
                if (c + 1 > rowA)     sacc[nt][1] = -1e30f;
                if (c     > rowA + 8) sacc[nt][2] = -1e30f;
                if (c + 1 > rowA + 8) sacc[nt][3] = -1e30f;
            }
        }

        // ---- online softmax ----
        float mA = -1e30f, mB = -1e30f;
#pragma unroll
        for (int nt = 0; nt < 8; nt++) {
            mA = fmaxf(mA, fmaxf(sacc[nt][0], sacc[nt][1]));
            mB = fmaxf(mB, fmaxf(sacc[nt][2], sacc[nt][3]));
        }
        mA = fmaxf(mA, __shfl_xor_sync(0xffffffffu, mA, 1));
        mA = fmaxf(mA, __shfl_xor_sync(0xffffffffu, mA, 2));
        mB = fmaxf(mB, __shfl_xor_sync(0xffffffffu, mB, 1));
        mB = fmaxf(mB, __shfl_xor_sync(0xffffffffu, mB, 2));

        float Mn0 = fmaxf(M0, mA), Mn1 = fmaxf(M1, mB);
        float f0 = __expf(M0 - Mn0), f1 = __expf(M1 - Mn1);
        M0 = Mn0; M1 = Mn1;
        ls0 *= f0; ls1 *= f1;
#pragma unroll
        for (int nt = 0; nt < 8; nt++) {
            oacc[nt][0] *= f0; oacc[nt][1] *= f0;
            oacc[nt][2] *= f1; oacc[nt][3] *= f1;
        }

        uint32_t pa[4][4];
#pragma unroll
        for (int ks = 0; ks < 4; ks++) {
            float e00 = __expf(sacc[2 * ks][0] - M0);
            float e01 = __expf(sacc[2 * ks][1] - M0);
            float e02 = __expf(sacc[2 * ks][2] - M1);
            float e03 = __expf(sacc[2 * ks][3] - M1);
            float e10 = __expf(sacc[2 * ks + 1][0] - M0);
            float e11 = __expf(sacc[2 * ks + 1][1] - M0);
            float e12 = __expf(sacc[2 * ks + 1][2] - M1);
            float e13 = __expf(sacc[2 * ks + 1][3] - M1);
            ls0 += e00 + e01 + e10 + e11;
            ls1 += e02 + e03 + e12 + e13;
            pa[ks][0] = packh2(e00, e01);
            pa[ks][1] = packh2(e02, e03);
            pa[ks][2] = packh2(e10, e11);
            pa[ks][3] = packh2(e12, e13);
        }

        // ---- O += P V ----
        const uint32_t bvRowBase = (uint32_t)((lm & 1) * 8 + lj) * 128;
#pragma unroll
        for (int ks = 0; ks < 4; ks++) {
            uint32_t bv[4][4];
#pragma unroll
            for (int p = 0; p < 4; p++) {
                uint32_t row = ks * (16 * 128) + bvRowBase;
                uint32_t addr = sV + row + (uint32_t)(((p * 2 + (lm >> 1)) ^ lj) << 4);
                LDSM_X4T(bv[p][0], bv[p][1], bv[p][2], bv[p][3], addr);
            }
#pragma unroll
            for (int p = 0; p < 4; p++) {
                MMA_F16(oacc[2 * p],     pa[ks], bv[p][0], bv[p][1]);
                MMA_F16(oacc[2 * p + 1], pa[ks], bv[p][2], bv[p][3]);
            }
        }

        __syncthreads();
        if (t + 2 < ntiles) {
            ldtile16((t & 1) ? sK1 : sK0, Kg + (size_t)(t + 2) * ATILE, tid);
            ldtile16((t & 1) ? sV1 : sV0, Vg + (size_t)(t + 2) * ATILE, tid);
        }
        CP_COMMIT();
    }

    // ---- epilogue: normalize, write fp16 ctx [B,L,E] ----
    ls0 += __shfl_xor_sync(0xffffffffu, ls0, 1);
    ls0 += __shfl_xor_sync(0xffffffffu, ls0, 2);
    ls1 += __shfl_xor_sync(0xffffffffu, ls1, 1);
    ls1 += __shfl_xor_sync(0xffffffffu, ls1, 2);
    const float inv0 = 1.f / ls0, inv1 = 1.f / ls1;

    const int b = bh >> 4, hh = bh & 15;
    __half* oA = &O[((size_t)(b * Lz + rowA)) * Ez + hh * DKz];
    __half* oB = &O[((size_t)(b * Lz + rowA + 8)) * Ez + hh * DKz];
#pragma unroll
    for (int nt = 0; nt < 8; nt++) {
        const int d = nt * 8 + cq;
        *(__half2*)&oA[d] = __floats2half2_rn(oacc[nt][0] * inv0, oacc[nt][1] * inv0);
        *(__half2*)&oB[d] = __floats2half2_rn(oacc[nt][2] * inv1, oacc[nt][3] * inv1);
    }
}

// ---------------- launch ------------------------------------------------------
extern "C" void kernel_launch(void* const* d_in, const int* in_sizes, int n_in,
                              void* d_out, int out_size)
{
    (void)in_sizes; (void)n_in; (void)out_size;
    const float* query = (const float*)d_in[0];
    const float* key   = (const float*)d_in[1];
    const float* value = (const float*)d_in[2];
    const float* wq    = (const float*)d_in[3];
    const float* bq    = (const float*)d_in[4];
    const float* wk    = (const float*)d_in[5];
    const float* bk    = (const float*)d_in[6];
    const float* wv    = (const float*)d_in[7];
    const float* bv    = (const float*)d_in[8];
    const float* wo    = (const float*)d_in[9];
    const float* bo    = (const float*)d_in[10];
    const int*   isc   = (const int*)d_in[11];
    float* out = (float*)d_out;

    __half *qh, *kh, *vh, *ch, *xh, *wh;
    cudaGetSymbolAddress((void**)&qh, g_Qh);
    cudaGetSymbolAddress((void**)&kh, g_Kh);
    cudaGetSymbolAddress((void**)&vh, g_Vh);
    cudaGetSymbolAddress((void**)&ch, g_CTXh);
    cudaGetSymbolAddress((void**)&xh, g_Xh);
    cudaGetSymbolAddress((void**)&wh, g_Wh);

    cudaFuncSetAttribute(gemm_h_kernel,
                         cudaFuncAttributeMaxDynamicSharedMemorySize, GEMM_SMEM);

    // fp32 -> fp16 conversions
    const int nAct8 = (Mz * Ez) / 8;   // 1M
    const int nW8   = (Ez * Ez) / 8;   // 128K
    cvt_h_kernel<<<nAct8 / 256, 256>>>(xh + 0 * (size_t)Mz * Ez, query, nAct8);
    cvt_h_kernel<<<nAct8 / 256, 256>>>(xh + 1 * (size_t)Mz * Ez, key,   nAct8);
    cvt_h_kernel<<<nAct8 / 256, 256>>>(xh + 2 * (size_t)Mz * Ez, value, nAct8);
    cvt_h_kernel<<<nW8 / 256, 256>>>(wh + 0 * (size_t)Ez * Ez, wq, nW8);
    cvt_h_kernel<<<nW8 / 256, 256>>>(wh + 1 * (size_t)Ez * Ez, wk, nW8);
    cvt_h_kernel<<<nW8 / 256, 256>>>(wh + 2 * (size_t)Ez * Ez, wv, nW8);
    cvt_h_kernel<<<nW8 / 256, 256>>>(wh + 3 * (size_t)Ez * Ez, wo, nW8);

    dim3 gg(Ez / TN, Mz / TM);   // (8, 64)
    gemm_h_kernel<<<gg, 256, GEMM_SMEM>>>(xh + 0 * (size_t)Mz * Ez,
                                          wh + 0 * (size_t)Ez * Ez, bq, qh, 1, 0.125f);
    gemm_h_kernel<<<gg, 256, GEMM_SMEM>>>(xh + 1 * (size_t)Mz * Ez,
                                          wh + 1 * (size_t)Ez * Ez, bk, kh, 1, 1.0f);
    gemm_h_kernel<<<gg, 256, GEMM_SMEM>>>(xh + 2 * (size_t)Mz * Ez,
                                          wh + 2 * (size_t)Ez * Ez, bv, vh, 1, 1.0f);

    attn_f16_kernel<<<dim3(Lz / 64, Bz * Hz), 128>>>(qh, kh, vh, ch, isc);

    gemm_h_kernel<<<gg, 256, GEMM_SMEM>>>(ch, wh + 3 * (size_t)Ez * Ez, bo, out, 0, 1.0f);
}

// round 6
// speedup vs baseline: 10.0649x; 1.1311x over previous
#include <cuda_runtime.h>
#include <cuda_fp16.h>
#include <cstdint>
#include <cstddef>

// Problem constants
#define Bz 4
#define Lz 2048
#define Ez 1024
#define Hz 16
#define DKz 64
#define Mz (Bz * Lz)   // 8192

#define LOG2E 1.4426950408889634f

// ---------------- scratch (allocation-free: __device__ globals) --------------
__device__ __half g_QKVh[(size_t)3 * Mz * Ez];  // [B,H,L,DK] x {Q(pre-scaled),K,V}
__device__ __half g_CTXh[(size_t)Mz * Ez];      // [B,L,E] fp16 ctx
__device__ __half g_Xh[(size_t)3 * Mz * Ez];    // fp16 query,key,value
__device__ __half g_Wh[(size_t)4 * Ez * Ez];    // fp16 wq,wk,wv,wo

// ============================ PTX helpers (base ISA only) ====================
__device__ __forceinline__ uint32_t smem_u32(const void* p) {
    uint32_t a;
    asm("{ .reg .u64 t; cvta.to.shared.u64 t, %1; cvt.u32.u64 %0, t; }"
        : "=r"(a) : "l"(p));
    return a;
}
#define CP_ASYNC16(dst, src) \
    asm volatile("cp.async.cg.shared.global [%0], [%1], 16;" :: "r"(dst), "l"(src))
#define CP_COMMIT() asm volatile("cp.async.commit_group;" ::: "memory")
#define CP_WAIT_1() asm volatile("cp.async.wait_group 1;" ::: "memory")
#define CP_WAIT_2() asm volatile("cp.async.wait_group 2;" ::: "memory")

#define LDSM_X4(r0, r1, r2, r3, addr) \
    asm volatile("ldmatrix.sync.aligned.m8n8.x4.shared.b16 {%0,%1,%2,%3}, [%4];" \
        : "=r"(r0), "=r"(r1), "=r"(r2), "=r"(r3) : "r"(addr))
#define LDSM_X4T(r0, r1, r2, r3, addr) \
    asm volatile("ldmatrix.sync.aligned.m8n8.x4.trans.shared.b16 {%0,%1,%2,%3}, [%4];" \
        : "=r"(r0), "=r"(r1), "=r"(r2), "=r"(r3) : "r"(addr))

#define MMA_F16(d, a, bv0, bv1) \
    asm volatile("mma.sync.aligned.m16n8k16.row.col.f32.f16.f16.f32 " \
        "{%0,%1,%2,%3}, {%4,%5,%6,%7}, {%8,%9}, {%0,%1,%2,%3};" \
        : "+f"((d)[0]), "+f"((d)[1]), "+f"((d)[2]), "+f"((d)[3]) \
        : "r"((a)[0]), "r"((a)[1]), "r"((a)[2]), "r"((a)[3]), "r"(bv0), "r"(bv1))

#define EX2_F16X2(x) asm("ex2.approx.f16x2 %0, %0;" : "+r"(x))

__device__ __forceinline__ uint32_t packh2(float a, float b) {
    __half2 h = __floats2half2_rn(a, b);
    return *(uint32_t*)&h;
}

// ====================== fp32 -> fp16 convert passes ==========================
// Activations: z selects {query,key,value}; dst is contiguous arena.
__global__ void __launch_bounds__(256) cvt_act_kernel(
    __half* __restrict__ dst, const float* __restrict__ s0,
    const float* __restrict__ s1, const float* __restrict__ s2)
{
    const int z = blockIdx.z;
    const float* src = z == 0 ? s0 : (z == 1 ? s1 : s2);
    __half* d = dst + (size_t)z * Mz * Ez;
    int i = blockIdx.x * blockDim.x + threadIdx.x;   // uint4 index (8 halves)
    float4 a = ((const float4*)src)[2 * i];
    float4 b = ((const float4*)src)[2 * i + 1];
    uint4 o;
    o.x = packh2(a.x, a.y); o.y = packh2(a.z, a.w);
    o.z = packh2(b.x, b.y); o.w = packh2(b.z, b.w);
    ((uint4*)d)[i] = o;
}

__global__ void __launch_bounds__(256) cvt_w_kernel(
    __half* __restrict__ dst, const float* __restrict__ s0,
    const float* __restrict__ s1, const float* __restrict__ s2,
    const float* __restrict__ s3)
{
    const int z = blockIdx.z;
    const float* src = z == 0 ? s0 : (z == 1 ? s1 : (z == 2 ? s2 : s3));
    __half* d = dst + (size_t)z * Ez * Ez;
    int i = blockIdx.x * blockDim.x + threadIdx.x;
    float4 a = ((const float4*)src)[2 * i];
    float4 b = ((const float4*)src)[2 * i + 1];
    uint4 o;
    o.x = packh2(a.x, a.y); o.y = packh2(a.z, a.w);
    o.z = packh2(b.x, b.y); o.w = packh2(b.z, b.w);
    ((uint4*)d)[i] = o;
}

// ====================== fp16 mma.sync GEMM ===================================
// C[m,n] = (sum_k A[m,k] * W[n,k] + bias[n]) * oscale
// CTA tile 128x128, BK=64 halves, 3-stage cp.async, 8 warps (4m x 2n).
#define TM 128
#define TN 128
#define BKh 64
#define NKCH (Ez / BKh)            // 16
#define HSTG (128 * 64 * 2)        // 16384 B per stage per operand
#define GEMM_SMEM (6 * HSTG)       // 98304 B (3 stages x {A,B})

__device__ __forceinline__ void ld_stage_h(uint32_t dstbase,
                                           const __half* __restrict__ src, int tid)
{
#pragma unroll
    for (int i = 0; i < 4; i++) {
        int idx = tid + i * 256;
        int row = idx >> 3, ch = idx & 7;
        uint32_t dst = dstbase + row * 128 + ((ch ^ (row & 7)) << 4);
        CP_ASYNC16(dst, src + (size_t)row * Ez + ch * 8);
    }
}

// Fused-QKV variant: gridDim.z selects activation/weight/bias/output.
// omode 1: write fp16 [B,H,L,DK] into qkv arena slot z. Q slot gets qscale.
__global__ void __launch_bounds__(256, 2) gemm_qkv_kernel(
    const __half* __restrict__ X, const __half* __restrict__ Wt,
    const float* __restrict__ b0, const float* __restrict__ b1,
    const float* __restrict__ b2, __half* __restrict__ qkv, float qscale)
{
    extern __shared__ char smem[];
    const uint32_t sb = smem_u32(smem);
    const int z = blockIdx.z;
    const __half* A = X + (size_t)z * Mz * Ez;
    const __half* W = Wt + (size_t)z * Ez * Ez;
    const float* bias = z == 0 ? b0 : (z == 1 ? b1 : b2);
    __half* Ch = qkv + (size_t)z * Mz * Ez;
    const float oscale = z == 0 ? qscale : 1.0f;

    const int tid  = threadIdx.x;
    const int wid  = tid >> 5, lane = tid & 31;
    const int wm = wid & 3, wn = wid >> 2;
    const int lj = lane & 7, lm = lane >> 3;
    const int m0 = blockIdx.y * TM, n0 = blockIdx.x * TN;

    const __half* Ag = A + (size_t)m0 * Ez;
    const __half* Wg = W + (size_t)n0 * Ez;

    float acc[2][8][4];
#pragma unroll
    for (int mt = 0; mt < 2; mt++)
#pragma unroll
        for (int nt = 0; nt < 8; nt++)
#pragma unroll
            for (int j = 0; j < 4; j++) acc[mt][nt][j] = 0.f;

#pragma unroll
    for (int s = 0; s < 3; s++) {
        ld_stage_h(sb + (2 * s) * HSTG, Ag + s * BKh, tid);
        ld_stage_h(sb + (2 * s + 1) * HSTG, Wg + s * BKh, tid);
        CP_COMMIT();
    }

    const uint32_t aRow = (uint32_t)(wm * 32 + (lm & 1) * 8 + lj) * 128;
    const uint32_t bRow = (uint32_t)(wn * 64 + (lm >> 1) * 8 + lj) * 128;
    const int aChHi = lm >> 1, bChHi = lm & 1;

    int st = 0;
#pragma unroll 1
    for (int k = 0; k < NKCH; k++) {
        const uint32_t sA = sb + (2 * st) * HSTG;
        const uint32_t sB = sb + (2 * st + 1) * HSTG;
        CP_WAIT_2();
        __syncthreads();

#pragma unroll
        for (int ks = 0; ks < 4; ks++) {
            uint32_t ar[2][4];
#pragma unroll
            for (int mt = 0; mt < 2; mt++) {
                uint32_t addr = sA + aRow + mt * (16 * 128)
                              + (uint32_t)(((ks * 2 + aChHi) ^ lj) << 4);
                LDSM_X4(ar[mt][0], ar[mt][1], ar[mt][2], ar[mt][3], addr);
            }
            uint32_t br[4][4];
#pragma unroll
            for (int p = 0; p < 4; p++) {
                uint32_t addr = sB + bRow + p * (16 * 128)
                              + (uint32_t)(((ks * 2 + bChHi) ^ lj) << 4);
                LDSM_X4(br[p][0], br[p][1], br[p][2], br[p][3], addr);
            }
#pragma unroll
            for (int mt = 0; mt < 2; mt++)
#pragma unroll
                for (int p = 0; p < 4; p++) {
                    MMA_F16(acc[mt][2 * p],     ar[mt], br[p][0], br[p][1]);
                    MMA_F16(acc[mt][2 * p + 1], ar[mt], br[p][2], br[p][3]);
                }
        }
        __syncthreads();
        if (k + 3 < NKCH) {
            ld_stage_h(sA, Ag + (size_t)(k + 3) * BKh, tid);
            ld_stage_h(sB, Wg + (size_t)(k + 3) * BKh, tid);
        }
        CP_COMMIT();
        st = (st == 2) ? 0 : st + 1;
    }

    const int g = lane >> 2, cq = (lane & 3) * 2;
#pragma unroll
    for (int mt = 0; mt < 2; mt++)
#pragma unroll
        for (int nt = 0; nt < 8; nt++) {
            const int n = n0 + wn * 64 + nt * 8 + cq;
            const float bx = bias[n], by = bias[n + 1];
#pragma unroll
            for (int hf = 0; hf < 2; hf++) {
                const int m = m0 + wm * 32 + mt * 16 + g + hf * 8;
                float vx = (acc[mt][nt][hf * 2 + 0] + bx) * oscale;
                float vy = (acc[mt][nt][hf * 2 + 1] + by) * oscale;
                int b = m >> 11, l = m & 2047, hh = n >> 6, d = n & 63;
                __half2 hv = __floats2half2_rn(vx, vy);
                *(__half2*)&Ch[(((size_t)(b * Hz + hh)) * Lz + l) * DKz + d] = hv;
            }
        }
}

// Output projection: fp16 in, fp32 out [M, E].
__global__ void __launch_bounds__(256, 2) gemm_out_kernel(
    const __half* __restrict__ A, const __half* __restrict__ W,
    const float* __restrict__ bias, float* __restrict__ C)
{
    extern __shared__ char smem[];
    const uint32_t sb = smem_u32(smem);
    const int tid  = threadIdx.x;
    const int wid  = tid >> 5, lane = tid & 31;
    const int wm = wid & 3, wn = wid >> 2;
    const int lj = lane & 7, lm = lane >> 3;
    const int m0 = blockIdx.y * TM, n0 = blockIdx.x * TN;

    const __half* Ag = A + (size_t)m0 * Ez;
    const __half* Wg = W + (size_t)n0 * Ez;

    float acc[2][8][4];
#pragma unroll
    for (int mt = 0; mt < 2; mt++)
#pragma unroll
        for (int nt = 0; nt < 8; nt++)
#pragma unroll
            for (int j = 0; j < 4; j++) acc[mt][nt][j] = 0.f;

#pragma unroll
    for (int s = 0; s < 3; s++) {
        ld_stage_h(sb + (2 * s) * HSTG, Ag + s * BKh, tid);
        ld_stage_h(sb + (2 * s + 1) * HSTG, Wg + s * BKh, tid);
        CP_COMMIT();
    }

    const uint32_t aRow = (uint32_t)(wm * 32 + (lm & 1) * 8 + lj) * 128;
    const uint32_t bRow = (uint32_t)(wn * 64 + (lm >> 1) * 8 + lj) * 128;
    const int aChHi = lm >> 1, bChHi = lm & 1;

    int st = 0;
#pragma unroll 1
    for (int k = 0; k < NKCH; k++) {
        const uint32_t sA = sb + (2 * st) * HSTG;
        const uint32_t sB = sb + (2 * st + 1) * HSTG;
        CP_WAIT_2();
        __syncthreads();

#pragma unroll
        for (int ks = 0; ks < 4; ks++) {
            uint32_t ar[2][4];
#pragma unroll
            for (int mt = 0; mt < 2; mt++) {
                uint32_t addr = sA + aRow + mt * (16 * 128)
                              + (uint32_t)(((ks * 2 + aChHi) ^ lj) << 4);
                LDSM_X4(ar[mt][0], ar[mt][1], ar[mt][2], ar[mt][3], addr);
            }
            uint32_t br[4][4];
#pragma unroll
            for (int p = 0; p < 4; p++) {
                uint32_t addr = sB + bRow + p * (16 * 128)
                              + (uint32_t)(((ks * 2 + bChHi) ^ lj) << 4);
                LDSM_X4(br[p][0], br[p][1], br[p][2], br[p][3], addr);
            }
#pragma unroll
            for (int mt = 0; mt < 2; mt++)
#pragma unroll
                for (int p = 0; p < 4; p++) {
                    MMA_F16(acc[mt][2 * p],     ar[mt], br[p][0], br[p][1]);
                    MMA_F16(acc[mt][2 * p + 1], ar[mt], br[p][2], br[p][3]);
                }
        }
        __syncthreads();
        if (k + 3 < NKCH) {
            ld_stage_h(sA, Ag + (size_t)(k + 3) * BKh, tid);
            ld_stage_h(sB, Wg + (size_t)(k + 3) * BKh, tid);
        }
        CP_COMMIT();
        st = (st == 2) ? 0 : st + 1;
    }

    const int g = lane >> 2, cq = (lane & 3) * 2;
#pragma unroll
    for (int mt = 0; mt < 2; mt++)
#pragma unroll
        for (int nt = 0; nt < 8; nt++) {
            const int n = n0 + wn * 64 + nt * 8 + cq;
            const float bx = bias[n], by = bias[n + 1];
#pragma unroll
            for (int hf = 0; hf < 2; hf++) {
                const int m = m0 + wm * 32 + mt * 16 + g + hf * 8;
                float2 v;
                v.x = acc[mt][nt][hf * 2 + 0] + bx;
                v.y = acc[mt][nt][hf * 2 + 1] + by;
                *(float2*)&C[(size_t)m * Ez + n] = v;
            }
        }
}

// ================= fp16 tensor-core flash attention (FA2-style) ==============
// Q pre-scaled by log2e/8 -> scores already in exp2 domain.
#define ATILE 4096   // 64 rows * 64 halves

__device__ __forceinline__ void ldtile16(uint32_t dst, const __half* __restrict__ src,
                                         int tid)
{
#pragma unroll
    for (int i = 0; i < 4; i++) {
        int idx = tid + i * 128;
        int row = idx >> 3, ch = idx & 7;
        CP_ASYNC16(dst + row * 128 + ((ch ^ (row & 7)) << 4),
                   src + (size_t)row * DKz + ch * 8);
    }
}

__global__ void __launch_bounds__(128) attn_f16_kernel(
    const __half* __restrict__ QKV, __half* __restrict__ O,
    const int* __restrict__ causal_p)
{
    __shared__ char sm[5 * 8192];   // Q + 2x K + 2x V
    const uint32_t sQ = smem_u32(sm);
    const uint32_t sK0 = sQ + 8192,  sK1 = sQ + 16384;
    const uint32_t sV0 = sQ + 24576, sV1 = sQ + 32768;

    const int tid = threadIdx.x, lane = tid & 31, wm = tid >> 5;
    const int lj = lane & 7, lm = lane >> 3;
    const int g = lane >> 2, cq = (lane & 3) * 2;
    const int qt = blockIdx.x, bh = blockIdx.y;
    const int q0 = qt * 64;
    const int causal = *causal_p;
    const int ntiles = causal ? (qt + 1) : (Lz / 64);

    const size_t base = (size_t)bh * Lz * DKz;
    const __half* Qg = QKV + base + (size_t)q0 * DKz;
    const __half* Kg = QKV + (size_t)Mz * Ez + base;
    const __half* Vg = QKV + (size_t)2 * Mz * Ez + base;

    ldtile16(sQ, Qg, tid);
    ldtile16(sK0, Kg, tid);
    ldtile16(sV0, Vg, tid);
    CP_COMMIT();
    if (ntiles > 1) { ldtile16(sK1, Kg + ATILE, tid); ldtile16(sV1, Vg + ATILE, tid); }
    CP_COMMIT();

    uint32_t aq[4][4];
    float oacc[8][4];
#pragma unroll
    for (int nt = 0; nt < 8; nt++)
#pragma unroll
        for (int j = 0; j < 4; j++) oacc[nt][j] = 0.f;
    float M0 = -1e30f, M1 = -1e30f, ls0 = 0.f, ls1 = 0.f;

    const int rowA = q0 + wm * 16 + g;
    const uint32_t aqRow = (uint32_t)(wm * 16 + (lm & 1) * 8 + lj) * 128;

#pragma unroll 1
    for (int t = 0; t < ntiles; t++) {
        const uint32_t sK = (t & 1) ? sK1 : sK0;
        const uint32_t sV = (t & 1) ? sV1 : sV0;
        CP_WAIT_1();
        __syncthreads();

        if (t == 0) {
#pragma unroll
            for (int ks = 0; ks < 4; ks++) {
                uint32_t addr = sQ + aqRow
                              + (uint32_t)(((ks * 2 + (lm >> 1)) ^ lj) << 4);
                LDSM_X4(aq[ks][0], aq[ks][1], aq[ks][2], aq[ks][3], addr);
            }
        }

        // ---- S = Q K^T (exp2 domain) ----
        float sacc[8][4];
#pragma unroll
        for (int nt = 0; nt < 8; nt++)
#pragma unroll
            for (int j = 0; j < 4; j++) sacc[nt][j] = 0.f;

        const uint32_t bkRowBase = (uint32_t)((lm >> 1) * 8 + lj) * 128;
#pragma unroll
        for (int ks = 0; ks < 4; ks++) {
            uint32_t bk[4][4];
#pragma unroll
            for (int p = 0; p < 4; p++) {
                uint32_t addr = sK + p * (16 * 128) + bkRowBase
                              + (uint32_t)(((ks * 2 + (lm & 1)) ^ lj) << 4);
                LDSM_X4(bk[p][0], bk[p][1], bk[p][2], bk[p][3], addr);
            }
#pragma unroll
            for (int p = 0; p < 4; p++) {
                MMA_F16(sacc[2 * p],     aq[ks], bk[p][0], bk[p][1]);
                MMA_F16(sacc[2 * p + 1], aq[ks], bk[p][2], bk[p][3]);
            }
        }

        // ---- causal mask (diagonal tile only) ----
        if (causal && t == qt) {
            const int colb = t * 64 + cq;
#pragma unroll
            for (int nt = 0; nt < 8; nt++) {
                int c = colb + nt * 8;
                if (c     > rowA)     sacc[nt][0] = -1e30f;
                if (c + 1 > rowA)     sacc[nt][1] = -1e30f;
                if (c     > rowA + 8) sacc[nt][2] = -1e30f;
                if (c + 1 > rowA + 8) sacc[nt][3] = -1e30f;
            }
        }

        // ---- online softmax (exp2 domain, f16x2 MUFU) ----
        float mA = -1e30f, mB = -1e30f;
#pragma unroll
        for (int nt = 0; nt < 8; nt++) {
            mA = fmaxf(mA, fmaxf(sacc[nt][0], sacc[nt][1]));
            mB = fmaxf(mB, fmaxf(sacc[nt][2], sacc[nt][3]));
        }
        mA = fmaxf(mA, __shfl_xor_sync(0xffffffffu, mA, 1));
        mA = fmaxf(mA, __shfl_xor_sync(0xffffffffu, mA, 2));
        mB = fmaxf(mB, __shfl_xor_sync(0xffffffffu, mB, 1));
        mB = fmaxf(mB, __shfl_xor_sync(0xffffffffu, mB, 2));

        float Mn0 = fmaxf(M0, mA), Mn1 = fmaxf(M1, mB);
        float f0 = exp2f(M0 - Mn0), f1 = exp2f(M1 - Mn1);
        M0 = Mn0; M1 = Mn1;
        ls0 *= f0; ls1 *= f1;
#pragma unroll
        for (int nt = 0; nt < 8; nt++) {
            oacc[nt][0] *= f0; oacc[nt][1] *= f0;
            oacc[nt][2] *= f1; oacc[nt][3] *= f1;
        }

        uint32_t pa[4][4];
        float tl0 = 0.f, tl1 = 0.f;
#pragma unroll
        for (int ks = 0; ks < 4; ks++) {
            uint32_t h00 = packh2(sacc[2 * ks][0] - M0, sacc[2 * ks][1] - M0);
            uint32_t h01 = packh2(sacc[2 * ks][2] - M1, sacc[2 * ks][3] - M1);
            uint32_t h10 = packh2(sacc[2 * ks + 1][0] - M0, sacc[2 * ks + 1][1] - M0);
            uint32_t h11 = packh2(sacc[2 * ks + 1][2] - M1, sacc[2 * ks + 1][3] - M1);
            EX2_F16X2(h00); EX2_F16X2(h01); EX2_F16X2(h10); EX2_F16X2(h11);
            pa[ks][0] = h00; pa[ks][1] = h01; pa[ks][2] = h10; pa[ks][3] = h11;
            float2 f00 = __half22float2(*(__half2*)&h00);
            float2 f01 = __half22float2(*(__half2*)&h01);
            float2 f10 = __half22float2(*(__half2*)&h10);
            float2 f11 = __half22float2(*(__half2*)&h11);
            tl0 += f00.x + f00.y + f10.x + f10.y;
            tl1 += f01.x + f01.y + f11.x + f11.y;
        }
        ls0 += tl0; ls1 += tl1;

        // ---- O += P V ----
        const uint32_t bvRowBase = (uint32_t)((lm & 1) * 8 + lj) * 128;
#pragma unroll
        for (int ks = 0; ks < 4; ks++) {
            uint32_t bv[4][4];
#pragma unroll
            for (int p = 0; p < 4; p++) {
                uint32_t row = ks * (16 * 128) + bvRowBase;
                uint32_t addr = sV + row + (uint32_t)(((p * 2 + (lm >> 1)) ^ lj) << 4);
                LDSM_X4T(bv[p][0], bv[p][1], bv[p][2], bv[p][3], addr);
            }
#pragma unroll
            for (int p = 0; p < 4; p++) {
                MMA_F16(oacc[2 * p],     pa[ks], bv[p][0], bv[p][1]);
                MMA_F16(oacc[2 * p + 1], pa[ks], bv[p][2], bv[p][3]);
            }
        }

        __syncthreads();
        if (t + 2 < ntiles) {
            ldtile16((t & 1) ? sK1 : sK0, Kg + (size_t)(t + 2) * ATILE, tid);
            ldtile16((t & 1) ? sV1 : sV0, Vg + (size_t)(t + 2) * ATILE, tid);
        }
        CP_COMMIT();
    }

    // ---- epilogue: normalize, write fp16 ctx [B,L,E] ----
    ls0 += __shfl_xor_sync(0xffffffffu, ls0, 1);
    ls0 += __shfl_xor_sync(0xffffffffu, ls0, 2);
    ls1 += __shfl_xor_sync(0xffffffffu, ls1, 1);
    ls1 += __shfl_xor_sync(0xffffffffu, ls1, 2);
    const float inv0 = 1.f / ls0, inv1 = 1.f / ls1;

    const int b = bh >> 4, hh = bh & 15;
    __half* oA = &O[((size_t)(b * Lz + rowA)) * Ez + hh * DKz];
    __half* oB = &O[((size_t)(b * Lz + rowA + 8)) * Ez + hh * DKz];
#pragma unroll
    for (int nt = 0; nt < 8; nt++) {
        const int d = nt * 8 + cq;
        *(__half2*)&oA[d] = __floats2half2_rn(oacc[nt][0] * inv0, oacc[nt][1] * inv0);
        *(__half2*)&oB[d] = __floats2half2_rn(oacc[nt][2] * inv1, oacc[nt][3] * inv1);
    }
}

// ---------------- launch ------------------------------------------------------
extern "C" void kernel_launch(void* const* d_in, const int* in_sizes, int n_in,
                              void* d_out, int out_size)
{
    (void)in_sizes; (void)n_in; (void)out_size;
    const float* query = (const float*)d_in[0];
    const float* key   = (const float*)d_in[1];
    const float* value = (const float*)d_in[2];
    const float* wq    = (const float*)d_in[3];
    const float* bq    = (const float*)d_in[4];
    const float* wk    = (const float*)d_in[5];
    const float* bk    = (const float*)d_in[6];
    const float* wv    = (const float*)d_in[7];
    const float* bv    = (const float*)d_in[8];
    const float* wo    = (const float*)d_in[9];
    const float* bo    = (const float*)d_in[10];
    const int*   isc   = (const int*)d_in[11];
    float* out = (float*)d_out;

    __half *qkv, *ch, *xh, *wh;
    cudaGetSymbolAddress((void**)&qkv, g_QKVh);
    cudaGetSymbolAddress((void**)&ch, g_CTXh);
    cudaGetSymbolAddress((void**)&xh, g_Xh);
    cudaGetSymbolAddress((void**)&wh, g_Wh);

    cudaFuncSetAttribute(gemm_qkv_kernel,
                         cudaFuncAttributeMaxDynamicSharedMemorySize, GEMM_SMEM);
    cudaFuncSetAttribute(gemm_out_kernel,
                         cudaFuncAttributeMaxDynamicSharedMemorySize, GEMM_SMEM);

    // fp32 -> fp16 conversions (2 launches)
    const int nAct8 = (Mz * Ez) / 8;   // 1M uint4 per tensor
    const int nW8   = (Ez * Ez) / 8;   // 128K uint4 per tensor
    cvt_act_kernel<<<dim3(nAct8 / 256, 1, 3), 256>>>(xh, query, key, value);
    cvt_w_kernel<<<dim3(nW8 / 256, 1, 4), 256>>>(wh, wq, wk, wv, wo);

    // fused QKV projections (Q pre-scaled into exp2 domain)
    dim3 gq(Ez / TN, Mz / TM, 3);   // (8, 64, 3)
    gemm_qkv_kernel<<<gq, 256, GEMM_SMEM>>>(xh, wh, bq, bk, bv, qkv,
                                            0.125f * LOG2E);

    attn_f16_kernel<<<dim3(Lz / 64, Bz * Hz), 128>>>(qkv, ch, isc);

    dim3 gg(Ez / TN, Mz / TM);      // (8, 64)
    gemm_out_kernel<<<gg, 256, GEMM_SMEM>>>(ch, wh + 3 * (size_t)Ez * Ez, bo, out);
}